// round 1
// baseline (speedup 1.0000x reference)
#include <cuda_runtime.h>

#define B_TOTAL 32768
#define F_TOTAL 200
#define D_IN    5
#define H_DIM   15
#define OUT_DIM 30
#define OPAD    32
#define FSPLIT  4
#define FCHUNK  (F_TOTAL / FSPLIT)   // 50
#define TPB     256

// Scratch (allocation-free rule: __device__ globals)
__device__ __align__(16) float g_W12[F_TOTAL * D_IN * OPAD];  // folded W1@W2, padded
__device__ __align__(16) float g_b12[F_TOTAL * OPAD];         // b1@W2 + b2, padded (0)
__device__ __align__(16) float g_W3p[F_TOTAL * OPAD];         // W3 padded (0)
__device__ __align__(16) float g_partial[FSPLIT][B_TOTAL];

// ---- packed f32x2 helpers (Blackwell FFMA2 path) ----
static __device__ __forceinline__ unsigned long long pk2(float x, float y) {
    unsigned long long r;
    asm("mov.b64 %0, {%1, %2};" : "=l"(r)
        : "r"(__float_as_uint(x)), "r"(__float_as_uint(y)));
    return r;
}
static __device__ __forceinline__ void upk2(unsigned long long v, float& x, float& y) {
    unsigned a, b;
    asm("mov.b64 {%0, %1}, %2;" : "=r"(a), "=r"(b) : "l"(v));
    x = __uint_as_float(a); y = __uint_as_float(b);
}
static __device__ __forceinline__ unsigned long long ffma2(
    unsigned long long a, unsigned long long b, unsigned long long c) {
    unsigned long long d;
    asm("fma.rn.f32x2 %0, %1, %2, %3;" : "=l"(d) : "l"(a), "l"(b), "l"(c));
    return d;
}

// ---- Kernel 1: fold W1@W2 (no ReLU between layers 1 and 2!) ----
// grid = F_TOTAL blocks x 160 threads. thread t -> (i = t/32, o = t%32).
__global__ void prep_kernel(const float* __restrict__ W1, const float* __restrict__ b1,
                            const float* __restrict__ W2, const float* __restrict__ b2,
                            const float* __restrict__ W3) {
    const int f = blockIdx.x;
    const int t = threadIdx.x;          // 0..159
    const int i = t >> 5, o = t & 31;
    const float* w1 = W1 + f * D_IN * H_DIM;
    const float* w2 = W2 + f * H_DIM * OUT_DIM;

    float s = 0.f;
    if (o < OUT_DIM) {
        #pragma unroll
        for (int h = 0; h < H_DIM; ++h) s += w1[i * H_DIM + h] * w2[h * OUT_DIM + o];
    }
    g_W12[(f * D_IN + i) * OPAD + o] = s;

    if (t < 32) {
        float sb = 0.f, w3v = 0.f;
        if (o < OUT_DIM) {
            #pragma unroll
            for (int h = 0; h < H_DIM; ++h) sb += b1[f * H_DIM + h] * w2[h * OUT_DIM + o];
            sb += b2[f * OUT_DIM + o];
            w3v = W3[f * OUT_DIM + o];
        }
        g_b12[f * OPAD + o] = sb;
        g_W3p[f * OPAD + o] = w3v;
    }
}

// ---- Kernel 2: main fused MLP. One thread per batch row, FSPLIT f-chunks over blockIdx.y ----
__global__ __launch_bounds__(TPB) void main_kernel(const float* __restrict__ y) {
    __shared__ __align__(16) float sW[FCHUNK * D_IN * OPAD];  // 32000 B
    __shared__ __align__(16) float sB[FCHUNK * OPAD];         // 6400 B
    __shared__ __align__(16) float sC[FCHUNK * OPAD];         // 6400 B

    const int fbase = blockIdx.y * FCHUNK;

    // cooperative smem fill (vectorized)
    {
        const float4* gw = (const float4*)(g_W12 + fbase * D_IN * OPAD);
        float4* sw4 = (float4*)sW;
        for (int t = threadIdx.x; t < FCHUNK * D_IN * OPAD / 4; t += TPB) sw4[t] = gw[t];
        const float4* gb = (const float4*)(g_b12 + fbase * OPAD);
        const float4* gc = (const float4*)(g_W3p + fbase * OPAD);
        float4* sb4 = (float4*)sB;
        float4* sc4 = (float4*)sC;
        for (int t = threadIdx.x; t < FCHUNK * OPAD / 4; t += TPB) {
            sb4[t] = gb[t];
            sc4[t] = gc[t];
        }
    }
    __syncthreads();

    const int b = blockIdx.x * TPB + threadIdx.x;
    const float* yrow = y + (size_t)b * (F_TOTAL * D_IN) + fbase * D_IN;

    unsigned long long accA = 0ull, accB = 0ull;   // bits of {0.f,0.f}

    #pragma unroll 1
    for (int f = 0; f < FCHUNK; ++f) {
        unsigned long long yp[D_IN];
        #pragma unroll
        for (int i = 0; i < D_IN; ++i) {
            float v = yrow[f * D_IN + i];
            yp[i] = pk2(v, v);
        }
        const ulonglong2* wp = (const ulonglong2*)(sW + f * D_IN * OPAD);
        const ulonglong2* bp = (const ulonglong2*)(sB + f * OPAD);
        const ulonglong2* cp = (const ulonglong2*)(sC + f * OPAD);

        #pragma unroll
        for (int j = 0; j < OPAD / 4; ++j) {       // 4 outputs (2 pairs) per j
            ulonglong2 t = bp[j];
            #pragma unroll
            for (int i = 0; i < D_IN; ++i) {
                ulonglong2 w = wp[i * (OPAD / 4) + j];   // LDS.128, broadcast
                t.x = ffma2(yp[i], w.x, t.x);
                t.y = ffma2(yp[i], w.y, t.y);
            }
            // ReLU (after 2nd linear, matching reference)
            float a0, a1, a2, a3;
            upk2(t.x, a0, a1);
            upk2(t.y, a2, a3);
            a0 = fmaxf(a0, 0.f); a1 = fmaxf(a1, 0.f);
            a2 = fmaxf(a2, 0.f); a3 = fmaxf(a3, 0.f);
            t.x = pk2(a0, a1);
            t.y = pk2(a2, a3);
            ulonglong2 c = cp[j];
            accA = ffma2(t.x, c.x, accA);
            accB = ffma2(t.y, c.y, accB);
        }
    }

    float r0, r1, r2, r3;
    upk2(accA, r0, r1);
    upk2(accB, r2, r3);
    g_partial[blockIdx.y][b] = (r0 + r1) + (r2 + r3);
}

// ---- Kernel 3: deterministic reduce of the f-split partials + b3 ----
__global__ void reduce_kernel(float* __restrict__ out, const float* __restrict__ b3) {
    const int i = blockIdx.x * blockDim.x + threadIdx.x;
    out[i] = ((g_partial[0][i] + g_partial[1][i]) +
              (g_partial[2][i] + g_partial[3][i])) + b3[0];
}

extern "C" void kernel_launch(void* const* d_in, const int* in_sizes, int n_in,
                              void* d_out, int out_size) {
    const float* y  = (const float*)d_in[0];
    const float* W1 = (const float*)d_in[1];
    const float* b1 = (const float*)d_in[2];
    const float* W2 = (const float*)d_in[3];
    const float* b2 = (const float*)d_in[4];
    const float* W3 = (const float*)d_in[5];
    const float* b3 = (const float*)d_in[6];
    float* out = (float*)d_out;

    prep_kernel<<<F_TOTAL, 160>>>(W1, b1, W2, b2, W3);

    dim3 grid(B_TOTAL / TPB, FSPLIT);
    main_kernel<<<grid, TPB>>>(y);

    reduce_kernel<<<B_TOTAL / 256, 256>>>(out, b3);
}

// round 2
// speedup vs baseline: 1.0024x; 1.0024x over previous
#include <cuda_runtime.h>

#define B_TOTAL 32768
#define F_TOTAL 200
#define D_IN    5
#define H_DIM   15
#define OUT_DIM 30
#define OPAD    32
#define FSPLIT  4
#define FCHUNK  (F_TOTAL / FSPLIT)   // 50
#define TPB     256

// Scratch (allocation-free rule: __device__ globals)
__device__ __align__(16) float g_W12[F_TOTAL * D_IN * OPAD];  // folded W1@W2, padded
__device__ __align__(16) float g_b12[F_TOTAL * OPAD];         // b1@W2 + b2, padded (0)
__device__ __align__(16) float g_W3p[F_TOTAL * OPAD];         // W3 padded (0)
__device__ __align__(16) float g_partial[FSPLIT][B_TOTAL];

// ---- packed f32x2 helpers (Blackwell FFMA2 path) ----
static __device__ __forceinline__ unsigned long long pk2(float x, float y) {
    unsigned long long r;
    asm("mov.b64 %0, {%1, %2};" : "=l"(r)
        : "r"(__float_as_uint(x)), "r"(__float_as_uint(y)));
    return r;
}
static __device__ __forceinline__ void upk2(unsigned long long v, float& x, float& y) {
    unsigned a, b;
    asm("mov.b64 {%0, %1}, %2;" : "=r"(a), "=r"(b) : "l"(v));
    x = __uint_as_float(a); y = __uint_as_float(b);
}
static __device__ __forceinline__ unsigned long long ffma2(
    unsigned long long a, unsigned long long b, unsigned long long c) {
    unsigned long long d;
    asm("fma.rn.f32x2 %0, %1, %2, %3;" : "=l"(d) : "l"(a), "l"(b), "l"(c));
    return d;
}

// ---- Kernel 1: fold W1@W2 (no ReLU between layers 1 and 2!) ----
// grid = F_TOTAL blocks x 160 threads. thread t -> (i = t/32, o = t%32).
__global__ void prep_kernel(const float* __restrict__ W1, const float* __restrict__ b1,
                            const float* __restrict__ W2, const float* __restrict__ b2,
                            const float* __restrict__ W3) {
    const int f = blockIdx.x;
    const int t = threadIdx.x;          // 0..159
    const int i = t >> 5, o = t & 31;
    const float* w1 = W1 + f * D_IN * H_DIM;
    const float* w2 = W2 + f * H_DIM * OUT_DIM;

    float s = 0.f;
    if (o < OUT_DIM) {
        #pragma unroll
        for (int h = 0; h < H_DIM; ++h) s += w1[i * H_DIM + h] * w2[h * OUT_DIM + o];
    }
    g_W12[(f * D_IN + i) * OPAD + o] = s;

    if (t < 32) {
        float sb = 0.f, w3v = 0.f;
        if (o < OUT_DIM) {
            #pragma unroll
            for (int h = 0; h < H_DIM; ++h) sb += b1[f * H_DIM + h] * w2[h * OUT_DIM + o];
            sb += b2[f * OUT_DIM + o];
            w3v = W3[f * OUT_DIM + o];
        }
        g_b12[f * OPAD + o] = sb;
        g_W3p[f * OPAD + o] = w3v;
    }
}

// ---- Kernel 2: main fused MLP. One thread per batch row, FSPLIT f-chunks over blockIdx.y ----
__global__ __launch_bounds__(TPB) void main_kernel(const float* __restrict__ y) {
    __shared__ __align__(16) float sW[FCHUNK * D_IN * OPAD];  // 32000 B
    __shared__ __align__(16) float sB[FCHUNK * OPAD];         // 6400 B
    __shared__ __align__(16) float sC[FCHUNK * OPAD];         // 6400 B

    const int fbase = blockIdx.y * FCHUNK;

    // cooperative smem fill (vectorized)
    {
        const float4* gw = (const float4*)(g_W12 + fbase * D_IN * OPAD);
        float4* sw4 = (float4*)sW;
        for (int t = threadIdx.x; t < FCHUNK * D_IN * OPAD / 4; t += TPB) sw4[t] = gw[t];
        const float4* gb = (const float4*)(g_b12 + fbase * OPAD);
        const float4* gc = (const float4*)(g_W3p + fbase * OPAD);
        float4* sb4 = (float4*)sB;
        float4* sc4 = (float4*)sC;
        for (int t = threadIdx.x; t < FCHUNK * OPAD / 4; t += TPB) {
            sb4[t] = gb[t];
            sc4[t] = gc[t];
        }
    }
    __syncthreads();

    const int b = blockIdx.x * TPB + threadIdx.x;
    const float* yrow = y + (size_t)b * (F_TOTAL * D_IN) + fbase * D_IN;

    unsigned long long accA = 0ull, accB = 0ull;   // bits of {0.f,0.f}

    #pragma unroll 1
    for (int f = 0; f < FCHUNK; ++f) {
        unsigned long long yp[D_IN];
        #pragma unroll
        for (int i = 0; i < D_IN; ++i) {
            float v = yrow[f * D_IN + i];
            yp[i] = pk2(v, v);
        }
        const ulonglong2* wp = (const ulonglong2*)(sW + f * D_IN * OPAD);
        const ulonglong2* bp = (const ulonglong2*)(sB + f * OPAD);
        const ulonglong2* cp = (const ulonglong2*)(sC + f * OPAD);

        #pragma unroll
        for (int j = 0; j < OPAD / 4; ++j) {       // 4 outputs (2 pairs) per j
            ulonglong2 t = bp[j];
            #pragma unroll
            for (int i = 0; i < D_IN; ++i) {
                ulonglong2 w = wp[i * (OPAD / 4) + j];   // LDS.128, broadcast
                t.x = ffma2(yp[i], w.x, t.x);
                t.y = ffma2(yp[i], w.y, t.y);
            }
            // ReLU (after 2nd linear, matching reference)
            float a0, a1, a2, a3;
            upk2(t.x, a0, a1);
            upk2(t.y, a2, a3);
            a0 = fmaxf(a0, 0.f); a1 = fmaxf(a1, 0.f);
            a2 = fmaxf(a2, 0.f); a3 = fmaxf(a3, 0.f);
            t.x = pk2(a0, a1);
            t.y = pk2(a2, a3);
            ulonglong2 c = cp[j];
            accA = ffma2(t.x, c.x, accA);
            accB = ffma2(t.y, c.y, accB);
        }
    }

    float r0, r1, r2, r3;
    upk2(accA, r0, r1);
    upk2(accB, r2, r3);
    g_partial[blockIdx.y][b] = (r0 + r1) + (r2 + r3);
}

// ---- Kernel 3: deterministic reduce of the f-split partials + b3 ----
__global__ void reduce_kernel(float* __restrict__ out, const float* __restrict__ b3) {
    const int i = blockIdx.x * blockDim.x + threadIdx.x;
    out[i] = ((g_partial[0][i] + g_partial[1][i]) +
              (g_partial[2][i] + g_partial[3][i])) + b3[0];
}

extern "C" void kernel_launch(void* const* d_in, const int* in_sizes, int n_in,
                              void* d_out, int out_size) {
    const float* y  = (const float*)d_in[0];
    const float* W1 = (const float*)d_in[1];
    const float* b1 = (const float*)d_in[2];
    const float* W2 = (const float*)d_in[3];
    const float* b2 = (const float*)d_in[4];
    const float* W3 = (const float*)d_in[5];
    const float* b3 = (const float*)d_in[6];
    float* out = (float*)d_out;

    prep_kernel<<<F_TOTAL, 160>>>(W1, b1, W2, b2, W3);

    dim3 grid(B_TOTAL / TPB, FSPLIT);
    main_kernel<<<grid, TPB>>>(y);

    reduce_kernel<<<B_TOTAL / 256, 256>>>(out, b3);
}